// round 4
// baseline (speedup 1.0000x reference)
#include <cuda_runtime.h>
#include <cuda_bf16.h>
#include <cstddef>

// Fused YOLOv3 decode, all 3 scales, one kernel.
// Scales 26 & 52 (95% of the data): one thread per (anchor, quad of 4 cells),
// channels loaded as float4 (LDG.128) -> 4x bytes in flight per load slot,
// 4x fewer address ops. Scale 13 (HW=169, not /4): scalar path, 1 cell/thread.

__device__ __forceinline__ float sigmoidf_(float x) { return 1.0f / (1.0f + expf(-x)); }

__global__ __launch_bounds__(256)
void yolo_decode_v4(const float* __restrict__ o13,
                    const float* __restrict__ o26,
                    const float* __restrict__ o52,
                    const float* __restrict__ a13,
                    const float* __restrict__ a26,
                    const float* __restrict__ a52,
                    const float* __restrict__ threshp,
                    const int*   __restrict__ casep,
                    float* __restrict__ boxes,   // [N,6]
                    float* __restrict__ mask,    // [N]
                    int B)
{
    const int tid = blockIdx.x * blockDim.x + threadIdx.x;

    const int C13 = B * 13 * 13;
    const int C26 = B * 26 * 26;
    const int C52 = B * 52 * 52;
    const int n13  = 3 * C13;            // scalar work items
    const int n26q = 3 * (C26 >> 2);     // quad work items (scale 26)
    const int n52q = 3 * (C52 >> 2);     // quad work items (scale 52)
    if (tid >= n13 + n26q + n52q) return;

    // scalar constants
    const int iv = __ldg(casep);
    const float case_f = (iv > 0 && iv < 1000000) ? (float)iv : __int_as_float(iv);
    const float inv_case = 1.0f / case_f;
    const float thresh = __ldg(threshp);

    if (tid < n13) {
        // ---------------- scalar path, 13x13 ----------------
        const int a     = tid / C13;
        const int local = tid - a * C13;
        const int HW = 169, S = 13;
        const int b   = local / HW;
        const int pos = local - b * HW;
        const int h   = pos / S;
        const int w   = pos - h * S;
        const float scale = 32.0f * inv_case;

        const float* p = o13 + (size_t)(b * 255 + a * 85) * HW + pos;

        const float v0 = __ldg(p);
        const float v1 = __ldg(p + HW);
        const float v2 = __ldg(p + 2 * HW);
        const float v3 = __ldg(p + 3 * HW);
        const float v4 = __ldg(p + 4 * HW);

        float maxv = -3.4e38f; int cls = 0;
        #pragma unroll
        for (int d0 = 0; d0 < 80; d0 += 16) {
            float v[16];
            #pragma unroll
            for (int i = 0; i < 16; ++i) v[i] = __ldg(p + (5 + d0 + i) * HW);
            #pragma unroll
            for (int i = 0; i < 16; ++i)
                if (v[i] > maxv) { maxv = v[i]; cls = d0 + i; }
        }

        const int row = local * 3 + a;
        float* r = boxes + (size_t)row * 6;
        r[0] = sigmoidf_(v0);
        r[1] = ((float)w + v1) * scale;
        r[2] = ((float)h + v2) * scale;
        r[3] = __ldg(a13 + a * 2 + 0) * expf(v3) * inv_case;
        r[4] = __ldg(a13 + a * 2 + 1) * expf(v4) * inv_case;
        r[5] = (float)cls;
        mask[row] = (v0 > thresh) ? 1.0f : 0.0f;
        return;
    }

    // ---------------- vector path (float4), 26 or 52 ----------------
    const float* in; const float* anch;
    int S, HW, Cq, q, rowoff; float t;
    if (tid < n13 + n26q) {
        in = o26; anch = a26; S = 26; HW = 676;  Cq = C26 >> 2;
        q = tid - n13;        rowoff = C13 * 3;         t = 16.0f;
    } else {
        in = o52; anch = a52; S = 52; HW = 2704; Cq = C52 >> 2;
        q = tid - n13 - n26q; rowoff = (C13 + C26) * 3; t = 8.0f;
    }
    const float scale = t * inv_case;

    const int a     = q / Cq;
    const int quad  = q - a * Cq;
    const int local = quad << 2;            // first of 4 consecutive cells
    const int b     = local / HW;
    const int pos   = local - b * HW;       // pos % 4 == 0, pos+3 < HW

    const float* p = in + (size_t)(b * 255 + a * 85) * HW + pos;  // 16B aligned

    // 5 box channels, vectorized
    const float4 q0 = *(const float4*)(p);
    const float4 q1 = *(const float4*)(p + HW);
    const float4 q2 = *(const float4*)(p + 2 * HW);
    const float4 q3 = *(const float4*)(p + 3 * HW);
    const float4 q4 = *(const float4*)(p + 4 * HW);

    // argmax over 80 class channels for 4 lanes at once, 8-channel batches
    float mx0 = -3.4e38f, mx1 = -3.4e38f, mx2 = -3.4e38f, mx3 = -3.4e38f;
    int   c0 = 0, c1 = 0, c2 = 0, c3 = 0;
    #pragma unroll
    for (int d0 = 0; d0 < 80; d0 += 8) {
        float4 v[8];
        #pragma unroll
        for (int i = 0; i < 8; ++i)
            v[i] = *(const float4*)(p + (5 + d0 + i) * HW);
        #pragma unroll
        for (int i = 0; i < 8; ++i) {
            const int d = d0 + i;
            if (v[i].x > mx0) { mx0 = v[i].x; c0 = d; }
            if (v[i].y > mx1) { mx1 = v[i].y; c1 = d; }
            if (v[i].z > mx2) { mx2 = v[i].z; c2 = d; }
            if (v[i].w > mx3) { mx3 = v[i].w; c3 = d; }
        }
    }

    const float ax = __ldg(anch + a * 2 + 0);
    const float ay = __ldg(anch + a * 2 + 1);

    // per-cell w,h with at most one row carry inside the quad
    const int h0 = pos / S;
    const int w0 = pos - h0 * S;

    const float ox[4] = {q1.x, q1.y, q1.z, q1.w};
    const float oy[4] = {q2.x, q2.y, q2.z, q2.w};
    const float ow[4] = {q3.x, q3.y, q3.z, q3.w};
    const float oh[4] = {q4.x, q4.y, q4.z, q4.w};
    const float oo[4] = {q0.x, q0.y, q0.z, q0.w};
    const int   cl[4] = {c0, c1, c2, c3};

    #pragma unroll
    for (int i = 0; i < 4; ++i) {
        int wi = w0 + i, hi = h0;
        if (wi >= S) { wi -= S; hi += 1; }

        const int row = rowoff + (local + i) * 3 + a;
        float* r = boxes + (size_t)row * 6;
        r[0] = sigmoidf_(oo[i]);
        r[1] = ((float)wi + ox[i]) * scale;
        r[2] = ((float)hi + oy[i]) * scale;
        r[3] = ax * expf(ow[i]) * inv_case;
        r[4] = ay * expf(oh[i]) * inv_case;
        r[5] = (float)cl[i];
        mask[row] = (oo[i] > thresh) ? 1.0f : 0.0f;
    }
}

extern "C" void kernel_launch(void* const* d_in, const int* in_sizes, int n_in,
                              void* d_out, int out_size)
{
    const float* o13 = (const float*)d_in[0];
    const float* o26 = (const float*)d_in[1];
    const float* o52 = (const float*)d_in[2];
    const float* a13 = (const float*)d_in[3];
    const float* a26 = (const float*)d_in[4];
    const float* a52 = (const float*)d_in[5];
    const float* th  = (const float*)d_in[6];
    const int*   cs  = (const int*)  d_in[7];

    const int B = in_sizes[0] / (255 * 13 * 13);

    const int C13 = B * 13 * 13;
    const int C26 = B * 26 * 26;
    const int C52 = B * 52 * 52;
    const int N = (C13 + C26 + C52) * 3;

    float* boxes = (float*)d_out;                   // [N,6]
    float* mask  = (float*)d_out + (size_t)N * 6;   // [N]

    const int threads = 3 * C13 + 3 * (C26 >> 2) + 3 * (C52 >> 2);
    const int TPB = 256;
    yolo_decode_v4<<<(threads + TPB - 1) / TPB, TPB>>>(
        o13, o26, o52, a13, a26, a52, th, cs, boxes, mask, B);
}

// round 5
// speedup vs baseline: 1.1152x; 1.1152x over previous
#include <cuda_runtime.h>
#include <cuda_bf16.h>
#include <cstddef>

// Fused YOLOv3 decode, all 3 scales, one kernel.
// Scales 26 & 52: one thread per (anchor, PAIR of 2 cells), channels loaded as
// float2 -> 2x bytes in flight per load and half the address ALU of the scalar
// version, while keeping ~700 blocks for occupancy (float4 variant collapsed
// to 381 blocks / 124 regs and regressed).
// Scale 13 (HW=169 odd): scalar path.
// __expf used throughout (rel_err budget 1e-3; measured 8e-10 with expf).

__device__ __forceinline__ float sigf(float x) { return 1.0f / (1.0f + __expf(-x)); }

__global__ __launch_bounds__(256)
void yolo_decode_p2(const float* __restrict__ o13,
                    const float* __restrict__ o26,
                    const float* __restrict__ o52,
                    const float* __restrict__ a13,
                    const float* __restrict__ a26,
                    const float* __restrict__ a52,
                    const float* __restrict__ threshp,
                    const int*   __restrict__ casep,
                    float* __restrict__ boxes,   // [N,6]
                    float* __restrict__ mask,    // [N]
                    int B)
{
    const int tid = blockIdx.x * blockDim.x + threadIdx.x;

    const int C13 = B * 13 * 13;
    const int C26 = B * 26 * 26;
    const int C52 = B * 52 * 52;
    const int n13  = 3 * C13;          // scalar items
    const int n26p = 3 * (C26 >> 1);   // pair items
    const int n52p = 3 * (C52 >> 1);
    if (tid >= n13 + n26p + n52p) return;

    const int iv = __ldg(casep);
    const float case_f = (iv > 0 && iv < 1000000) ? (float)iv : __int_as_float(iv);
    const float inv_case = 1.0f / case_f;
    const float thresh = __ldg(threshp);

    if (tid < n13) {
        // ---------------- scalar path, 13x13 ----------------
        const int a     = tid / C13;
        const int local = tid - a * C13;
        const int HW = 169, S = 13;
        const int b   = local / HW;
        const int pos = local - b * HW;
        const int h   = pos / S;
        const int w   = pos - h * S;
        const float scale = 32.0f * inv_case;

        const float* p = o13 + (size_t)(b * 255 + a * 85) * HW + pos;

        const float v0 = __ldg(p);
        const float v1 = __ldg(p + HW);
        const float v2 = __ldg(p + 2 * HW);
        const float v3 = __ldg(p + 3 * HW);
        const float v4 = __ldg(p + 4 * HW);

        float maxv = -3.4e38f; int cls = 0;
        #pragma unroll
        for (int d0 = 0; d0 < 80; d0 += 16) {
            float v[16];
            #pragma unroll
            for (int i = 0; i < 16; ++i) v[i] = __ldg(p + (5 + d0 + i) * HW);
            #pragma unroll
            for (int i = 0; i < 16; ++i)
                if (v[i] > maxv) { maxv = v[i]; cls = d0 + i; }
        }

        const int row = local * 3 + a;
        float* r = boxes + (size_t)row * 6;
        r[0] = sigf(v0);
        r[1] = ((float)w + v1) * scale;
        r[2] = ((float)h + v2) * scale;
        r[3] = __ldg(a13 + a * 2 + 0) * __expf(v3) * inv_case;
        r[4] = __ldg(a13 + a * 2 + 1) * __expf(v4) * inv_case;
        r[5] = (float)cls;
        mask[row] = (v0 > thresh) ? 1.0f : 0.0f;
        return;
    }

    // ---------------- pair path (float2), 26 or 52 ----------------
    const float* in; const float* anch;
    int S, HW, Cp, q, rowoff; float t;
    if (tid < n13 + n26p) {
        in = o26; anch = a26; S = 26; HW = 676;  Cp = C26 >> 1;
        q = tid - n13;        rowoff = C13 * 3;         t = 16.0f;
    } else {
        in = o52; anch = a52; S = 52; HW = 2704; Cp = C52 >> 1;
        q = tid - n13 - n26p; rowoff = (C13 + C26) * 3; t = 8.0f;
    }
    const float scale = t * inv_case;

    const int a     = q / Cp;
    const int pairi = q - a * Cp;
    const int local = pairi << 1;           // first of 2 consecutive cells
    const int b     = local / HW;
    const int pos   = local - b * HW;       // even; pos+1 < HW (HW even)

    const float* p = in + (size_t)(b * 255 + a * 85) * HW + pos;  // 8B aligned

    const float2 q0 = *(const float2*)(p);
    const float2 q1 = *(const float2*)(p + HW);
    const float2 q2 = *(const float2*)(p + 2 * HW);
    const float2 q3 = *(const float2*)(p + 3 * HW);
    const float2 q4 = *(const float2*)(p + 4 * HW);

    // argmax over 80 class channels for both cells, 8-channel batches (MLP=8 float2)
    float mx0 = -3.4e38f, mx1 = -3.4e38f;
    int   c0 = 0, c1 = 0;
    #pragma unroll
    for (int d0 = 0; d0 < 80; d0 += 8) {
        float2 v[8];
        #pragma unroll
        for (int i = 0; i < 8; ++i)
            v[i] = *(const float2*)(p + (5 + d0 + i) * HW);
        #pragma unroll
        for (int i = 0; i < 8; ++i) {
            const int d = d0 + i;
            if (v[i].x > mx0) { mx0 = v[i].x; c0 = d; }
            if (v[i].y > mx1) { mx1 = v[i].y; c1 = d; }
        }
    }

    const float ax = __ldg(anch + a * 2 + 0);
    const float ay = __ldg(anch + a * 2 + 1);

    const int h0 = pos / S;
    const int w0 = pos - h0 * S;

    // cell 0
    {
        const int row = rowoff + local * 3 + a;
        float* r = boxes + (size_t)row * 6;
        r[0] = sigf(q0.x);
        r[1] = ((float)w0 + q1.x) * scale;
        r[2] = ((float)h0 + q2.x) * scale;
        r[3] = ax * __expf(q3.x) * inv_case;
        r[4] = ay * __expf(q4.x) * inv_case;
        r[5] = (float)c0;
        mask[row] = (q0.x > thresh) ? 1.0f : 0.0f;
    }
    // cell 1 (handle row wrap w0+1 == S)
    {
        int w1 = w0 + 1, h1 = h0;
        if (w1 >= S) { w1 = 0; h1 += 1; }
        const int row = rowoff + (local + 1) * 3 + a;
        float* r = boxes + (size_t)row * 6;
        r[0] = sigf(q0.y);
        r[1] = ((float)w1 + q1.y) * scale;
        r[2] = ((float)h1 + q2.y) * scale;
        r[3] = ax * __expf(q3.y) * inv_case;
        r[4] = ay * __expf(q4.y) * inv_case;
        r[5] = (float)c1;
        mask[row] = (q0.y > thresh) ? 1.0f : 0.0f;
    }
}

extern "C" void kernel_launch(void* const* d_in, const int* in_sizes, int n_in,
                              void* d_out, int out_size)
{
    const float* o13 = (const float*)d_in[0];
    const float* o26 = (const float*)d_in[1];
    const float* o52 = (const float*)d_in[2];
    const float* a13 = (const float*)d_in[3];
    const float* a26 = (const float*)d_in[4];
    const float* a52 = (const float*)d_in[5];
    const float* th  = (const float*)d_in[6];
    const int*   cs  = (const int*)  d_in[7];

    const int B = in_sizes[0] / (255 * 13 * 13);

    const int C13 = B * 13 * 13;
    const int C26 = B * 26 * 26;
    const int C52 = B * 52 * 52;
    const int N = (C13 + C26 + C52) * 3;

    float* boxes = (float*)d_out;                   // [N,6]
    float* mask  = (float*)d_out + (size_t)N * 6;   // [N]

    const int threads = 3 * C13 + 3 * (C26 >> 1) + 3 * (C52 >> 1);
    const int TPB = 256;
    yolo_decode_p2<<<(threads + TPB - 1) / TPB, TPB>>>(
        o13, o26, o52, a13, a26, a52, th, cs, boxes, mask, B);
}

// round 6
// speedup vs baseline: 1.3467x; 1.2076x over previous
#include <cuda_runtime.h>
#include <cuda_bf16.h>
#include <cstddef>

// Fused YOLOv3 decode, all 3 scales, one kernel.
// R3 layout (best so far): one thread per (anchor, cell), anchor outermost so
// warp lanes read consecutive floats -> fully coalesced channel loads.
// This round: __launch_bounds__(256,6) to force regs<=42 (6 blocks/SM, 75%
// theoretical occ — R3 measured 48 regs / 51.6% occ and was latency-bound),
// argmax batch shrunk 16->10 to fit the register budget without spills,
// fast-math transcendentals (__expf; rel_err budget 1e-3, we're at 1e-9).

__device__ __forceinline__ float sigf(float x) { return 1.0f / (1.0f + __expf(-x)); }

__global__ __launch_bounds__(256, 6)
void yolo_decode_r6(const float* __restrict__ o13,
                    const float* __restrict__ o26,
                    const float* __restrict__ o52,
                    const float* __restrict__ a13,
                    const float* __restrict__ a26,
                    const float* __restrict__ a52,
                    const float* __restrict__ threshp,
                    const int*   __restrict__ casep,
                    float* __restrict__ boxes,   // [N,6]
                    float* __restrict__ mask,    // [N]
                    int B, int cells)
{
    const int tid = blockIdx.x * blockDim.x + threadIdx.x;
    if (tid >= 3 * cells) return;

    const int a    = tid / cells;       // anchor 0..2
    const int cell = tid - a * cells;   // global cell id

    const int C13 = B * 13 * 13;
    const int C26 = B * 26 * 26;

    // Resolve scale from cell id
    const float* in; const float* anch;
    int S, local, rowoff; float t;
    if (cell < C13)            { in = o13; anch = a13; S = 13; local = cell;              rowoff = 0;               t = 32.0f; }
    else if (cell < C13 + C26) { in = o26; anch = a26; S = 26; local = cell - C13;        rowoff = C13 * 3;         t = 16.0f; }
    else                       { in = o52; anch = a52; S = 52; local = cell - C13 - C26;  rowoff = (C13 + C26) * 3; t = 8.0f;  }

    const int HW  = S * S;
    const int b   = local / HW;
    const int pos = local - b * HW;
    const int h   = pos / S;
    const int w   = pos - h * S;

    // 'case' scalar: int 416 or float 416.0f (dtype-robust)
    const int iv = __ldg(casep);
    const float case_f = (iv > 0 && iv < 1000000) ? (float)iv : __int_as_float(iv);
    const float inv_case = 1.0f / case_f;
    const float scale = t * inv_case;
    const float thresh = __ldg(threshp);

    const float* p = in + (size_t)(b * 255 + a * 85) * HW + pos;

    const float o0 = __ldg(p);
    const float o1 = __ldg(p + HW);
    const float o2 = __ldg(p + 2 * HW);
    const float o3 = __ldg(p + 3 * HW);
    const float o4 = __ldg(p + 4 * HW);

    // Argmax over 80 class logits, 10-wide load batches (8 batches).
    // Strict '>' keeps FIRST max (jnp.argmax tie rule).
    float maxv = -3.4e38f;
    int   cls  = 0;
    const float* pc = p + 5 * HW;
    #pragma unroll
    for (int d0 = 0; d0 < 80; d0 += 10) {
        float v[10];
        #pragma unroll
        for (int i = 0; i < 10; ++i)
            v[i] = __ldg(pc + (d0 + i) * HW);
        #pragma unroll
        for (int i = 0; i < 10; ++i)
            if (v[i] > maxv) { maxv = v[i]; cls = d0 + i; }
    }

    const float prob = sigf(o0);
    const float cx = ((float)w + o1) * scale;
    const float cy = ((float)h + o2) * scale;
    const float bw = __ldg(anch + a * 2 + 0) * __expf(o3) * inv_case;
    const float bh = __ldg(anch + a * 2 + 1) * __expf(o4) * inv_case;

    const int row = rowoff + local * 3 + a;
    float* r = boxes + (size_t)row * 6;
    r[0] = prob;
    r[1] = cx;
    r[2] = cy;
    r[3] = bw;
    r[4] = bh;
    r[5] = (float)cls;

    mask[row] = (o0 > thresh) ? 1.0f : 0.0f;
}

extern "C" void kernel_launch(void* const* d_in, const int* in_sizes, int n_in,
                              void* d_out, int out_size)
{
    const float* o13 = (const float*)d_in[0];
    const float* o26 = (const float*)d_in[1];
    const float* o52 = (const float*)d_in[2];
    const float* a13 = (const float*)d_in[3];
    const float* a26 = (const float*)d_in[4];
    const float* a52 = (const float*)d_in[5];
    const float* th  = (const float*)d_in[6];
    const int*   cs  = (const int*)  d_in[7];

    const int B = in_sizes[0] / (255 * 13 * 13);

    const int C13 = B * 13 * 13;
    const int C26 = B * 26 * 26;
    const int C52 = B * 52 * 52;
    const int cells = C13 + C26 + C52;
    const int N = cells * 3;

    float* boxes = (float*)d_out;                   // [N,6]
    float* mask  = (float*)d_out + (size_t)N * 6;   // [N]

    const int TPB = 256;
    const int threads = 3 * cells;
    yolo_decode_r6<<<(threads + TPB - 1) / TPB, TPB>>>(
        o13, o26, o52, a13, a26, a52, th, cs, boxes, mask, B, cells);
}